// round 14
// baseline (speedup 1.0000x reference)
#include <cuda_runtime.h>
#include <math.h>
#include <stdint.h>

// Problem constants
#define NB   64      // num_groups (B)
#define NG   32      // group_size (G)
#define ND   2000    // output dim (D)
#define NM   16      // m_samples
#define NE   16      // noise dim
#define NDIN 256
#define KTOT 272     // DIN + E
#define EPSC 1e-12f
#define NCH  8       // loss d-chunks
#define CHD  250     // d per chunk
#define SPD  253     // sP stride (odd -> conflict-free)
#define NDH  1000    // d per IPF cluster rank
#define RCH  250     // rounding chunk columns

// ---------------- scratch (device globals; referenced directly by kernels) ----------------
__device__ __align__(16) float g_Xs[NB * NDIN];    // sum over g of x            [64,256]
__device__ __align__(16) float g_Ns[NB * NM * NE]; // sum over g of noise_loss   [1024,16]
__device__ __align__(16) float g_Tp[4][NB * ND];   // k-split partials of Xs·W1  4x[64,2000]
__device__ __align__(16) float g_Y [NB * NG * ND]; // x_pred (softplus)          [2048,2000]
__device__ float g_lossInn[NB * NCH * 256];
__device__ float g_lossTd [NB * NCH * 16];
__device__ float g_lossPart[NB];

__device__ __forceinline__ uint32_t smem_u32(const void* p) {
    uint32_t a;
    asm("{ .reg .u64 t; cvta.to.shared.u64 t, %1; cvt.u32.u64 %0, t; }" : "=r"(a) : "l"(p));
    return a;
}
__device__ __forceinline__ uint32_t mapa_u32(uint32_t addr, uint32_t rank) {
    uint32_t r;
    asm("mapa.shared::cluster.u32 %0, %1, %2;" : "=r"(r) : "r"(addr), "r"(rank));
    return r;
}

// ---------------- stage 1: group reductions ----------------
__global__ void k_reduce(const float* __restrict__ x, const float* __restrict__ nl) {
    int i = blockIdx.x * 256 + threadIdx.x;
    if (i < NB * NDIN) {
        int b = i >> 8, k = i & 255;
        float s = 0.f;
        #pragma unroll 8
        for (int g = 0; g < NG; g++) s += x[(size_t)(b * NG + g) * NDIN + k];
        g_Xs[i] = s;
    } else {
        int j = i - NB * NDIN;             // j < 1024*16
        int row = j >> 4, e = j & 15;      // row = b*16 + m
        int b = row >> 4, m = row & 15;
        float s = 0.f;
        #pragma unroll 8
        for (int g = 0; g < NG; g++) s += nl[(size_t)((b * NG + g) * NM + m) * NE + e];
        g_Ns[j] = s;
    }
}

// ---------------- stage 2a: tiny GEMM, k-split x4: Tp[kb][b,d] = Xs[b,k0:k0+64]·W1 --------
__global__ void k_gemmT(const float* __restrict__ W, const float* __restrict__ bias) {
    __shared__ float sXs[8 * 64];          // [b_local][k_local]
    const int tid = threadIdx.x;
    const int dblk = blockIdx.x, bblk = blockIdx.y, kblk = blockIdx.z;
    const int k0 = kblk * 64;
    #pragma unroll
    for (int i = tid; i < 8 * 64; i += 256) {
        int bl = i >> 6, kk = i & 63;
        sXs[i] = g_Xs[(bblk * 8 + bl) * NDIN + k0 + kk];
    }
    __syncthreads();
    int d = dblk * 256 + tid;
    bool v = d < ND;
    float acc[8];
    #pragma unroll
    for (int i = 0; i < 8; i++) acc[i] = 0.f;
    #pragma unroll 8
    for (int k = 0; k < 64; k++) {
        float w = v ? W[(size_t)(k0 + k) * ND + d] : 0.f;
        #pragma unroll
        for (int i = 0; i < 8; i++) acc[i] = fmaf(sXs[i * 64 + k], w, acc[i]);
    }
    if (v) {
        float add = (kblk == 0) ? 32.f * bias[d] : 0.f;
        #pragma unroll
        for (int i = 0; i < 8; i++)
            g_Tp[kblk][(size_t)(bblk * 8 + i) * ND + d] = acc[i] + add;
    }
}

// ---------------- stage 2b: sample GEMM (fp32, packed f32x2 FMA, 2-stage pipeline) -------
__global__ void __launch_bounds__(256, 2)
k_gemm1(const float* __restrict__ x, const float* __restrict__ ns,
        const float* __restrict__ W, const float* __restrict__ bias) {
    __shared__ __align__(16) float As[2][16 * 128];  // [buf][k][m]
    __shared__ __align__(16) float Bs[2][16 * 128];  // [buf][k][n]
    const int tid = threadIdx.x;                  // 256 threads
    const int bn = blockIdx.x, bm = blockIdx.y;
    const int tr = tid >> 4, tc = tid & 15;

    auto loadA = [&](int kt, int i) -> float4 {
        int idx = tid + i * 256;
        int kq = idx >> 7, row = idx & 127;
        int rowG = bm * 128 + row;
        if (kt < 16)
            return *(const float4*)(x + (size_t)rowG * NDIN + kt * 16 + kq * 4);
        return *(const float4*)(ns + (size_t)rowG * NE + kq * 4);
    };
    auto loadB = [&](int kt, int i) -> float4 {
        int idx = tid + i * 256;
        int kr = idx >> 5, cq = idx & 31;
        int d = bn * 128 + cq * 4;
        if (d < ND) return *(const float4*)(W + (size_t)(kt * 16 + kr) * ND + d);
        return make_float4(0.f, 0.f, 0.f, 0.f);
    };
    auto storeA = [&](int buf, int i, float4 v) {
        int idx = tid + i * 256;
        int kq = idx >> 7, row = idx & 127;
        As[buf][(kq * 4 + 0) * 128 + row] = v.x;
        As[buf][(kq * 4 + 1) * 128 + row] = v.y;
        As[buf][(kq * 4 + 2) * 128 + row] = v.z;
        As[buf][(kq * 4 + 3) * 128 + row] = v.w;
    };
    auto storeB = [&](int buf, int i, float4 v) {
        int idx = tid + i * 256;
        int kr = idx >> 5, cq = idx & 31;
        *(float4*)(&Bs[buf][kr * 128 + cq * 4]) = v;
    };

    unsigned long long acc2[8][4];       // packed f32x2 accumulators
    #pragma unroll
    for (int i = 0; i < 8; i++)
        #pragma unroll
        for (int j = 0; j < 4; j++) acc2[i][j] = 0ull;

    float4 pa0 = loadA(0, 0), pa1 = loadA(0, 1);
    float4 pb0 = loadB(0, 0), pb1 = loadB(0, 1);
    storeA(0, 0, pa0); storeA(0, 1, pa1);
    storeB(0, 0, pb0); storeB(0, 1, pb1);
    __syncthreads();

    for (int kt = 0; kt < 17; kt++) {             // 272 = 17 * 16
        int cur = kt & 1;
        if (kt < 16) {
            pa0 = loadA(kt + 1, 0); pa1 = loadA(kt + 1, 1);
            pb0 = loadB(kt + 1, 0); pb1 = loadB(kt + 1, 1);
        }
        const float* Ab = As[cur];
        const float* Bb = Bs[cur];
        #pragma unroll
        for (int kk = 0; kk < 16; kk++) {
            float a[8];
            *(float4*)(a)     = *(const float4*)(Ab + kk * 128 + tr * 8);
            *(float4*)(a + 4) = *(const float4*)(Ab + kk * 128 + tr * 8 + 4);
            unsigned long long bp[4];
            {
                const float* bptr = Bb + kk * 128 + tc * 8;
                ulonglong2 t0 = *(const ulonglong2*)(bptr);
                ulonglong2 t1 = *(const ulonglong2*)(bptr + 4);
                bp[0] = t0.x; bp[1] = t0.y; bp[2] = t1.x; bp[3] = t1.y;
            }
            #pragma unroll
            for (int ii = 0; ii < 8; ii++) {
                unsigned long long ap;
                asm("mov.b64 %0, {%1, %1};" : "=l"(ap) : "f"(a[ii]));
                #pragma unroll
                for (int j = 0; j < 4; j++)
                    asm("fma.rn.f32x2 %0, %1, %2, %0;"
                        : "+l"(acc2[ii][j]) : "l"(ap), "l"(bp[j]));
            }
        }
        if (kt < 16) {
            storeA(cur ^ 1, 0, pa0); storeA(cur ^ 1, 1, pa1);
            storeB(cur ^ 1, 0, pb0); storeB(cur ^ 1, 1, pb1);
            __syncthreads();
        }
    }
    #pragma unroll
    for (int ii = 0; ii < 8; ii++) {
        int row = bm * 128 + tr * 8 + ii;
        #pragma unroll
        for (int j = 0; j < 4; j++) {
            float lo, hi;
            asm("mov.b64 {%0, %1}, %2;" : "=f"(lo), "=f"(hi) : "l"(acc2[ii][j]));
            int col = bn * 128 + tc * 8 + 2 * j;
            if (col < ND) {
                float z = lo + bias[col];
                g_Y[(size_t)row * ND + col] = fmaxf(z, 0.f) + log1pf(expf(-fabsf(z)));
            }
            if (col + 1 < ND) {
                float z = hi + bias[col + 1];
                g_Y[(size_t)row * ND + col + 1] = fmaxf(z, 0.f) + log1pf(expf(-fabsf(z)));
            }
        }
    }
}

// ---------------- stage 3a: loss partials, P built on the fly ----------------
__global__ void __launch_bounds__(256, 4)
k_loss_part(const float* __restrict__ target, const float* __restrict__ W) {
    const int ch = blockIdx.x, b = blockIdx.y;
    const int tid = threadIdx.x;        // 256
    const int m = tid >> 4, n = tid & 15;
    const int dStart = ch * CHD;
    __shared__ float sP[16 * SPD];
    __shared__ float sT[CHD];
    __shared__ float sNs[256];          // [m][e]

    sNs[tid] = g_Ns[b * 256 + tid];
    __syncthreads();

    if (tid < CHD) {
        int dd = tid, d = dStart + dd;
        float p[16];
        float t0 = g_Tp[0][(size_t)b * ND + d] + g_Tp[1][(size_t)b * ND + d]
                 + g_Tp[2][(size_t)b * ND + d] + g_Tp[3][(size_t)b * ND + d];
        #pragma unroll
        for (int mm = 0; mm < 16; mm++) p[mm] = t0;
        #pragma unroll
        for (int e = 0; e < 16; e++) {
            float w = W[(size_t)(256 + e) * ND + d];
            #pragma unroll
            for (int mm = 0; mm < 16; mm++)
                p[mm] = fmaf(sNs[mm * 16 + e], w, p[mm]);
        }
        #pragma unroll
        for (int mm = 0; mm < 16; mm++) sP[mm * SPD + dd] = p[mm];
        sT[dd] = target[(size_t)b * ND + d];
    }
    __syncthreads();

    float inn = 0.f, td = 0.f;
    #pragma unroll 2
    for (int dd = 0; dd < CHD; dd++) {
        float pm = sP[m * SPD + dd], pn = sP[n * SPD + dd];
        inn = fmaf(pm, pn, inn);
        if (m == n) { float df = pm - sT[dd]; td = fmaf(df, df, td); }
    }
    g_lossInn[(b * NCH + ch) * 256 + tid] = inn;
    if (m == n) g_lossTd[(b * NCH + ch) * 16 + m] = td;
}

// ---------------- stage 3b: loss combine per b ----------------
__global__ void k_loss_comb() {
    const int b = blockIdx.x;
    const int tid = threadIdx.x;        // 256
    const int m = tid >> 4, n = tid & 15;
    __shared__ float s_sq[16], s_td[16], s_w[8];

    float inn = 0.f;
    #pragma unroll
    for (int ch = 0; ch < NCH; ch++) inn += g_lossInn[(b * NCH + ch) * 256 + tid];
    if (m == n) {
        float td = 0.f;
        #pragma unroll
        for (int ch = 0; ch < NCH; ch++) td += g_lossTd[(b * NCH + ch) * 16 + m];
        s_sq[m] = inn; s_td[m] = td;
    }
    __syncthreads();
    float pd = 0.f;
    if (m != n) pd = sqrtf(fmaxf(s_sq[m] + s_sq[n] - 2.f * inn, 1e-6f));
    #pragma unroll
    for (int o = 16; o; o >>= 1) pd += __shfl_xor_sync(0xffffffffu, pd, o);
    if ((tid & 31) == 0) s_w[tid >> 5] = pd;
    __syncthreads();
    if (tid == 0) {
        float tot = 0.f;
        for (int w = 0; w < 8; w++) tot += s_w[w];
        float tc = 0.f;
        for (int mm = 0; mm < 16; mm++) tc += sqrtf(s_td[mm]);
        g_lossPart[b] = tc / 16.f - 0.5f * (tot / 240.f);   // LAM/2=0.5, M*(M-1)=240
    }
}

__global__ void k_loss_final(float* __restrict__ out, int off) {
    if (off >= 1 && threadIdx.x == 0 && blockIdx.x == 0) {
        float s = 0.f;
        for (int i = 0; i < NB; i++) s += g_lossPart[i];   // fixed order -> deterministic
        out[0] = s / (float)NB;
    }
}

// ---- multi-value butterfly: reduce 16 row sums across a warp in 16 shfls ----
__device__ __forceinline__ void warp_reduce16(float v[16], int lane,
                                              float& out, int& gheld) {
    const unsigned FULL = 0xffffffffu;
    #pragma unroll
    for (int i = 0; i < 8; i++) {
        float send = (lane & 16) ? v[i] : v[i + 8];
        float recv = __shfl_xor_sync(FULL, send, 16);
        v[i] = ((lane & 16) ? v[i + 8] : v[i]) + recv;
    }
    #pragma unroll
    for (int i = 0; i < 4; i++) {
        float send = (lane & 8) ? v[i] : v[i + 4];
        float recv = __shfl_xor_sync(FULL, send, 8);
        v[i] = ((lane & 8) ? v[i + 4] : v[i]) + recv;
    }
    #pragma unroll
    for (int i = 0; i < 2; i++) {
        float send = (lane & 4) ? v[i] : v[i + 2];
        float recv = __shfl_xor_sync(FULL, send, 4);
        v[i] = ((lane & 4) ? v[i + 2] : v[i]) + recv;
    }
    {
        float send = (lane & 2) ? v[0] : v[1];
        float recv = __shfl_xor_sync(FULL, send, 2);
        v[0] = ((lane & 2) ? v[1] : v[0]) + recv;
    }
    v[0] += __shfl_xor_sync(FULL, v[0], 1);
    gheld = ((lane >> 1) & 1) | (((lane >> 2) & 1) << 1)
          | (((lane >> 3) & 1) << 2) | (((lane >> 4) & 1) << 3);
    out = v[0];
}

// ---------------- stage 4+5 fused: IPF (d-split cluster) + exact integerization ----------
// blockIdx.x = 2*b + rank; rank owns d in [rank*1000, rank*1000+1000) for ALL 32 g.
// Thread owns 2 d-columns (c*512 + tid) x 32 g -> 64 y registers.
// Column sums are CTA-local (no exchange); row sums exchange 32 floats via DSMEM per iter.
// Tail: smem-transpose 250-column chunks, warp-per-column rounding (lane=g), write out.
__global__ void __cluster_dims__(2, 1, 1) __launch_bounds__(512, 1)
k_ipf(const int* __restrict__ ts, float* __restrict__ out, int off) {
    const unsigned FULL = 0xffffffffu;
    const int tid = threadIdx.x, lane = tid & 31, warp = tid >> 5;
    uint32_t rank;
    asm("mov.u32 %0, %%cluster_ctarank;" : "=r"(rank));
    const int b = blockIdx.x >> 1;
    const int dBase = (int)rank * NDH;
    const float* yg = g_Y + (size_t)b * NG * ND;
    const int* tsb = ts + (size_t)b * ND;

    __shared__ float s_red[16 * 32];    // [warp][g]
    __shared__ float s_x[2][32];        // row-partial exchange (double-buffered)
    __shared__ float s_R[32], s_rowfac[32];
    __shared__ float sT[RCH * 33];      // rounding transpose buffer (33 KB)

    const uint32_t myX = smem_u32(&s_x[0][0]);
    const uint32_t peerX = mapa_u32(myX, rank ^ 1u);

    int dIdx[2]; bool val[2];
    float C0[2], colsum[2], yv[NG][2];
    #pragma unroll
    for (int c = 0; c < 2; c++) {
        int dl = c * 512 + tid;
        dIdx[c] = dBase + dl;
        val[c] = dl < NDH;
        C0[c] = val[c] ? fmaxf((float)__ldg(tsb + dIdx[c]), 0.f) : 0.f;
        colsum[c] = 0.f;
    }
    #pragma unroll
    for (int g = 0; g < NG; g++)
        #pragma unroll
        for (int c = 0; c < 2; c++) {
            yv[g][c] = val[c] ? fmaxf(yg[(size_t)g * ND + dIdx[c]], 0.f) : 0.f;
            colsum[c] += yv[g][c];
        }

    // ---- helper macro-ish lambda: reduce 32 per-thread row partials to s_red ----
    auto row_reduce_to_smem = [&]() {
        float v[16]; float o; int gh;
        #pragma unroll
        for (int i = 0; i < 16; i++) v[i] = yv[i][0] + yv[i][1];
        warp_reduce16(v, lane, o, gh);
        if (!(lane & 1)) s_red[warp * 32 + gh] = o;
        #pragma unroll
        for (int i = 0; i < 16; i++) v[i] = yv[16 + i][0] + yv[16 + i][1];
        warp_reduce16(v, lane, o, gh);
        if (!(lane & 1)) s_red[warp * 32 + 16 + gh] = o;
    };

    // initial row anchors R (global, pre-smoothing) — exchange buf 0
    row_reduce_to_smem();
    __syncthreads();
    if (tid < 32) {
        float s = 0.f;
        #pragma unroll
        for (int w = 0; w < 16; w++) s += s_red[w * 32 + tid];
        s_x[0][tid] = s;
    }
    asm volatile("barrier.cluster.arrive.aligned;" ::: "memory");
    asm volatile("barrier.cluster.wait.aligned;" ::: "memory");
    if (tid < 32) {
        float pv;
        asm volatile("ld.shared::cluster.f32 %0, [%1];"
                     : "=f"(pv) : "r"(peerX + (uint32_t)tid * 4u));
        s_R[tid] = s_x[0][tid] + pv;
    }
    __syncthreads();

    // col_zero smoothing (dead in practice — softplus > 0 — kept for exactness; local)
    #pragma unroll
    for (int c = 0; c < 2; c++) {
        if (val[c] && colsum[c] <= 0.f && C0[c] > 0.f) {
            #pragma unroll
            for (int g = 0; g < NG; g++) yv[g][c] += 1e-8f;
            colsum[c] += 32.f * 1e-8f;
        }
    }

    for (int it = 0; it < 60; it++) {
        // column factor: fully local
        float cf0 = fminf(fmaxf(C0[0] / fmaxf(colsum[0], EPSC), 0.75f), 1.25f);
        float cf1 = fminf(fmaxf(C0[1] / fmaxf(colsum[1], EPSC), 0.75f), 1.25f);
        #pragma unroll
        for (int g = 0; g < NG; g++) { yv[g][0] *= cf0; yv[g][1] *= cf1; }
        // row partials -> smem -> 32-float exchange
        row_reduce_to_smem();
        __syncthreads();
        int buf = (it + 1) & 1;
        if (tid < 32) {
            float s = 0.f;
            #pragma unroll
            for (int w = 0; w < 16; w++) s += s_red[w * 32 + tid];
            s_x[buf][tid] = s;
        }
        asm volatile("barrier.cluster.arrive.aligned;" ::: "memory");
        asm volatile("barrier.cluster.wait.aligned;" ::: "memory");
        if (tid < 32) {
            float pv;
            asm volatile("ld.shared::cluster.f32 %0, [%1];"
                         : "=f"(pv) : "r"(peerX + (uint32_t)(buf * 32 + tid) * 4u));
            float rowsum = s_x[buf][tid] + pv;
            s_rowfac[tid] = fminf(fmaxf(s_R[tid] / fmaxf(rowsum, EPSC), 0.75f), 1.25f);
        }
        __syncthreads();
        // row scale + local colsum recompute
        colsum[0] = 0.f; colsum[1] = 0.f;
        #pragma unroll
        for (int g = 0; g < NG; g++) {
            float rf = s_rowfac[g];
            float v0 = yv[g][0] * rf, v1 = yv[g][1] * rf;
            yv[g][0] = v0; yv[g][1] = v1;
            colsum[0] += v0; colsum[1] += v1;
        }
    }

    // final column normalization (no clamp) — local
    {
        float f0 = C0[0] / fmaxf(colsum[0], EPSC);
        float f1 = C0[1] / fmaxf(colsum[1], EPSC);
        #pragma unroll
        for (int g = 0; g < NG; g++) { yv[g][0] *= f0; yv[g][1] *= f1; }
    }

    // ---- fused exact integerization: 4 chunks of 250 columns ----
    int* sTi = (int*)sT;
    for (int chunk = 0; chunk < 4; chunk++) {
        int lo = chunk * RCH;
        __syncthreads();                 // previous chunk's output reads done
        // owners deposit their columns (conflict-free: stride 33)
        #pragma unroll
        for (int c = 0; c < 2; c++) {
            int dl = c * 512 + tid;
            int cl = dl - lo;
            if (cl >= 0 && cl < RCH) {
                #pragma unroll
                for (int g = 0; g < NG; g++) sT[cl * 33 + g] = yv[g][c];
            }
        }
        __syncthreads();
        // warp per column, lane = g
        for (int i = 0; i < 16; i++) {
            int cl = warp * 16 + i;
            if (cl < RCH) {
                int d = dBase + lo + cl;
                float v = fmaxf(sT[cl * 33 + lane], 0.f);
                float xf = floorf(v);
                int yi = (int)xf;
                float fr = v - xf;
                int t = tsb[d];          // warp-uniform broadcast load

                int s = __reduce_add_sync(FULL, yi);
                int need = t - s;
                int pos = need > 0 ? need : 0;
                int q = pos >> 5;
                yi += q;
                int r = pos - (q << 5);
                if (r > 0) {
                    int cnt = 0;
                    #pragma unroll
                    for (int k = 1; k < 32; k++) {
                        int j = (lane + k) & 31;
                        float o = __shfl_sync(FULL, fr, j);
                        cnt += (o > fr) || (o == fr && j < lane);
                    }
                    if (cnt < r) yi += 1;
                }

                int s2 = __reduce_add_sync(FULL, yi);
                int need2 = t - s2;
                int neg = need2 < 0 ? -need2 : 0;
                neg = neg < s2 ? neg : s2;
                if (neg > 0) {
                    int q2 = neg >> 5;
                    int yb = yi;
                    yi -= q2; if (yi < 0) yi = 0;
                    int removed = __reduce_add_sync(FULL, yb - yi);
                    int r2 = neg - removed;
                    if (r2 > 0) {
                        float fm = (yi > 0) ? fr : __int_as_float(0x7f800000);
                        int cnt2 = 0;
                        #pragma unroll
                        for (int k = 1; k < 32; k++) {
                            int j = (lane + k) & 31;
                            float o = __shfl_sync(FULL, fm, j);
                            cnt2 += (o < fm) || (o == fm && j < lane);
                        }
                        if (cnt2 < r2) yi -= 1;
                        if (yi < 0) yi = 0;
                    }
                }
                sTi[cl * 33 + lane] = yi;
            }
        }
        __syncthreads();
        // coalesced-ish output write: 32 g x 250 cols = 8000 ints
        for (int i = 0; i < 16; i++) {
            int idx = tid + i * 512;
            if (idx < NG * RCH) {
                int g = idx / RCH, cl = idx - g * RCH;
                out[(size_t)off + (size_t)(b * NG + g) * ND + dBase + lo + cl]
                    = (float)sTi[cl * 33 + g];
            }
        }
    }

    // peer must be done with all DSMEM reads before either CTA exits
    asm volatile("barrier.cluster.arrive.aligned;" ::: "memory");
    asm volatile("barrier.cluster.wait.aligned;" ::: "memory");
}

// ---------------- launch (pure kernel launches; no runtime API calls) ----------------
extern "C" void kernel_launch(void* const* d_in, const int* in_sizes, int n_in,
                              void* d_out, int out_size) {
    const float* x      = (const float*)d_in[0];   // [2048,256]
    const float* target = (const float*)d_in[1];   // [64,2000]
    const int*   tsum   = (const int*)  d_in[2];   // [64,2000]
    const float* W      = (const float*)d_in[3];   // [272,2000]
    const float* bias   = (const float*)d_in[4];   // [2000]
    const float* nl     = (const float*)d_in[5];   // [32768,16]
    const float* ns     = (const float*)d_in[6];   // [2048,16]
    float* out = (float*)d_out;

    int off = out_size - NB * NG * ND;             // expected 1 (loss scalar first)
    if (off < 0) off = 0;

    // 1) group reductions
    k_reduce<<<128, 256>>>(x, nl);
    // 2a) sample GEMM with softplus (f32x2 packed math): g_Y[2048,2000]
    k_gemm1<<<dim3(16, 16), 256>>>(x, ns, W, bias);
    // 2b) tiny loss-path GEMM, k-split x4: g_Tp
    k_gemmT<<<dim3(8, 8, 4), 256>>>(W, bias);
    // 3) loss: partials (P rebuilt on the fly) -> per-b combine -> final sum
    k_loss_part<<<dim3(NCH, NB), 256>>>(target, W);
    k_loss_comb<<<NB, 256>>>();
    k_loss_final<<<1, 32>>>(out, off);
    // 4+5) fused IPF (d-split cluster, local colsums) + exact rounding + output write
    k_ipf<<<2 * NB, 512>>>(tsum, out, off);
}

// round 17
// speedup vs baseline: 1.1332x; 1.1332x over previous
#include <cuda_runtime.h>
#include <math.h>
#include <stdint.h>

// Problem constants
#define NB   64      // num_groups (B)
#define NG   32      // group_size (G)
#define ND   2000    // output dim (D)
#define NM   16      // m_samples
#define NE   16      // noise dim
#define NDIN 256
#define KTOT 272     // DIN + E
#define EPSC 1e-12f
#define NCH  8       // loss d-chunks
#define CHD  250     // d per chunk
#define SPD  253     // sP stride (odd -> conflict-free)
#define NDH  1000    // d per IPF cluster rank

// ---------------- scratch (device globals; referenced directly by kernels) ----------------
__device__ __align__(16) float g_Tp[4][NB * ND];   // k-split partials of Xs·W1  4x[64,2000]
__device__ __align__(16) float g_Y [NB * NG * ND]; // x_pred -> IPF y (in place) [2048,2000]
__device__ float g_lossInn[NB * NCH * 256];
__device__ float g_lossTd [NB * NCH * 16];
__device__ float g_lossPart[NB];

__device__ __forceinline__ uint32_t smem_u32(const void* p) {
    uint32_t a;
    asm("{ .reg .u64 t; cvta.to.shared.u64 t, %1; cvt.u32.u64 %0, t; }" : "=r"(a) : "l"(p));
    return a;
}
__device__ __forceinline__ uint32_t mapa_u32(uint32_t addr, uint32_t rank) {
    uint32_t r;
    asm("mapa.shared::cluster.u32 %0, %1, %2;" : "=r"(r) : "r"(addr), "r"(rank));
    return r;
}

// ---------------- stage 2a: tiny GEMM, k-split x4 (group-reduce folded in) ---------------
// Tp[kb][b,d] = (sum_g x[b,g])·W1[k0:k0+64] ; grid (8 dblk, 8 bblk, 4 kblk)
__global__ void k_gemmT(const float* __restrict__ x, const float* __restrict__ W,
                        const float* __restrict__ bias) {
    __shared__ float sXs[8 * 64];          // [b_local][k_local]
    const int tid = threadIdx.x;
    const int dblk = blockIdx.x, bblk = blockIdx.y, kblk = blockIdx.z;
    const int k0 = kblk * 64;
    #pragma unroll
    for (int i = tid; i < 8 * 64; i += 256) {
        int bl = i >> 6, kk = i & 63;
        const float* xp = x + (size_t)((bblk * 8 + bl) * NG) * NDIN + k0 + kk;
        float s = 0.f;
        #pragma unroll 8
        for (int g = 0; g < NG; g++) s += xp[(size_t)g * NDIN];   // same order as reference
        sXs[i] = s;
    }
    __syncthreads();
    int d = dblk * 256 + tid;
    bool v = d < ND;
    float acc[8];
    #pragma unroll
    for (int i = 0; i < 8; i++) acc[i] = 0.f;
    #pragma unroll 8
    for (int k = 0; k < 64; k++) {
        float w = v ? W[(size_t)(k0 + k) * ND + d] : 0.f;
        #pragma unroll
        for (int i = 0; i < 8; i++) acc[i] = fmaf(sXs[i * 64 + k], w, acc[i]);
    }
    if (v) {
        float add = (kblk == 0) ? 32.f * bias[d] : 0.f;
        #pragma unroll
        for (int i = 0; i < 8; i++)
            g_Tp[kblk][(size_t)(bblk * 8 + i) * ND + d] = acc[i] + add;
    }
}

// ---------------- stage 2b: sample GEMM (fp32, packed f32x2 FMA, 2-stage pipeline) -------
__global__ void __launch_bounds__(256, 2)
k_gemm1(const float* __restrict__ x, const float* __restrict__ ns,
        const float* __restrict__ W, const float* __restrict__ bias) {
    __shared__ __align__(16) float As[2][16 * 128];  // [buf][k][m]
    __shared__ __align__(16) float Bs[2][16 * 128];  // [buf][k][n]
    const int tid = threadIdx.x;                  // 256 threads
    const int bn = blockIdx.x, bm = blockIdx.y;
    const int tr = tid >> 4, tc = tid & 15;

    auto loadA = [&](int kt, int i) -> float4 {
        int idx = tid + i * 256;
        int kq = idx >> 7, row = idx & 127;
        int rowG = bm * 128 + row;
        if (kt < 16)
            return *(const float4*)(x + (size_t)rowG * NDIN + kt * 16 + kq * 4);
        return *(const float4*)(ns + (size_t)rowG * NE + kq * 4);
    };
    auto loadB = [&](int kt, int i) -> float4 {
        int idx = tid + i * 256;
        int kr = idx >> 5, cq = idx & 31;
        int d = bn * 128 + cq * 4;
        if (d < ND) return *(const float4*)(W + (size_t)(kt * 16 + kr) * ND + d);
        return make_float4(0.f, 0.f, 0.f, 0.f);
    };
    auto storeA = [&](int buf, int i, float4 v) {
        int idx = tid + i * 256;
        int kq = idx >> 7, row = idx & 127;
        As[buf][(kq * 4 + 0) * 128 + row] = v.x;
        As[buf][(kq * 4 + 1) * 128 + row] = v.y;
        As[buf][(kq * 4 + 2) * 128 + row] = v.z;
        As[buf][(kq * 4 + 3) * 128 + row] = v.w;
    };
    auto storeB = [&](int buf, int i, float4 v) {
        int idx = tid + i * 256;
        int kr = idx >> 5, cq = idx & 31;
        *(float4*)(&Bs[buf][kr * 128 + cq * 4]) = v;
    };

    unsigned long long acc2[8][4];       // packed f32x2 accumulators
    #pragma unroll
    for (int i = 0; i < 8; i++)
        #pragma unroll
        for (int j = 0; j < 4; j++) acc2[i][j] = 0ull;

    float4 pa0 = loadA(0, 0), pa1 = loadA(0, 1);
    float4 pb0 = loadB(0, 0), pb1 = loadB(0, 1);
    storeA(0, 0, pa0); storeA(0, 1, pa1);
    storeB(0, 0, pb0); storeB(0, 1, pb1);
    __syncthreads();

    for (int kt = 0; kt < 17; kt++) {             // 272 = 17 * 16
        int cur = kt & 1;
        if (kt < 16) {
            pa0 = loadA(kt + 1, 0); pa1 = loadA(kt + 1, 1);
            pb0 = loadB(kt + 1, 0); pb1 = loadB(kt + 1, 1);
        }
        const float* Ab = As[cur];
        const float* Bb = Bs[cur];
        #pragma unroll
        for (int kk = 0; kk < 16; kk++) {
            float a[8];
            *(float4*)(a)     = *(const float4*)(Ab + kk * 128 + tr * 8);
            *(float4*)(a + 4) = *(const float4*)(Ab + kk * 128 + tr * 8 + 4);
            unsigned long long bp[4];
            {
                const float* bptr = Bb + kk * 128 + tc * 8;
                ulonglong2 t0 = *(const ulonglong2*)(bptr);
                ulonglong2 t1 = *(const ulonglong2*)(bptr + 4);
                bp[0] = t0.x; bp[1] = t0.y; bp[2] = t1.x; bp[3] = t1.y;
            }
            #pragma unroll
            for (int ii = 0; ii < 8; ii++) {
                unsigned long long ap;
                asm("mov.b64 %0, {%1, %1};" : "=l"(ap) : "f"(a[ii]));
                #pragma unroll
                for (int j = 0; j < 4; j++)
                    asm("fma.rn.f32x2 %0, %1, %2, %0;"
                        : "+l"(acc2[ii][j]) : "l"(ap), "l"(bp[j]));
            }
        }
        if (kt < 16) {
            storeA(cur ^ 1, 0, pa0); storeA(cur ^ 1, 1, pa1);
            storeB(cur ^ 1, 0, pb0); storeB(cur ^ 1, 1, pb1);
            __syncthreads();
        }
    }
    #pragma unroll
    for (int ii = 0; ii < 8; ii++) {
        int row = bm * 128 + tr * 8 + ii;
        #pragma unroll
        for (int j = 0; j < 4; j++) {
            float lo, hi;
            asm("mov.b64 {%0, %1}, %2;" : "=f"(lo), "=f"(hi) : "l"(acc2[ii][j]));
            int col = bn * 128 + tc * 8 + 2 * j;
            if (col < ND) {
                float z = lo + bias[col];
                g_Y[(size_t)row * ND + col] = fmaxf(z, 0.f) + log1pf(expf(-fabsf(z)));
            }
            if (col + 1 < ND) {
                float z = hi + bias[col + 1];
                g_Y[(size_t)row * ND + col + 1] = fmaxf(z, 0.f) + log1pf(expf(-fabsf(z)));
            }
        }
    }
}

// ---------------- stage 3a: loss partials (Ns group-reduce folded into prologue) ---------
__global__ void __launch_bounds__(256, 4)
k_loss_part(const float* __restrict__ target, const float* __restrict__ W,
            const float* __restrict__ nl) {
    const int ch = blockIdx.x, b = blockIdx.y;
    const int tid = threadIdx.x;        // 256
    const int m = tid >> 4, n = tid & 15;
    const int dStart = ch * CHD;
    __shared__ float sP[16 * SPD];
    __shared__ float sT[CHD];
    __shared__ float sNs[256];          // [m][e]

    {   // sNs[m*16+e] = sum_g nl[(b*32+g)*256 + m*16+e]  (same order as reference)
        const float* nlb = nl + (size_t)(b * NG) * 256 + tid;
        float s = 0.f;
        #pragma unroll 8
        for (int g = 0; g < NG; g++) s += nlb[(size_t)g * 256];
        sNs[tid] = s;
    }
    __syncthreads();

    if (tid < CHD) {
        int dd = tid, d = dStart + dd;
        float p[16];
        float t0 = g_Tp[0][(size_t)b * ND + d] + g_Tp[1][(size_t)b * ND + d]
                 + g_Tp[2][(size_t)b * ND + d] + g_Tp[3][(size_t)b * ND + d];
        #pragma unroll
        for (int mm = 0; mm < 16; mm++) p[mm] = t0;
        #pragma unroll
        for (int e = 0; e < 16; e++) {
            float w = W[(size_t)(256 + e) * ND + d];
            #pragma unroll
            for (int mm = 0; mm < 16; mm++)
                p[mm] = fmaf(sNs[mm * 16 + e], w, p[mm]);
        }
        #pragma unroll
        for (int mm = 0; mm < 16; mm++) sP[mm * SPD + dd] = p[mm];
        sT[dd] = target[(size_t)b * ND + d];
    }
    __syncthreads();

    float inn = 0.f, td = 0.f;
    #pragma unroll 2
    for (int dd = 0; dd < CHD; dd++) {
        float pm = sP[m * SPD + dd], pn = sP[n * SPD + dd];
        inn = fmaf(pm, pn, inn);
        if (m == n) { float df = pm - sT[dd]; td = fmaf(df, df, td); }
    }
    g_lossInn[(b * NCH + ch) * 256 + tid] = inn;
    if (m == n) g_lossTd[(b * NCH + ch) * 16 + m] = td;
}

// ---------------- stage 3b: loss combine per b ----------------
__global__ void k_loss_comb() {
    const int b = blockIdx.x;
    const int tid = threadIdx.x;        // 256
    const int m = tid >> 4, n = tid & 15;
    __shared__ float s_sq[16], s_td[16], s_w[8];

    float inn = 0.f;
    #pragma unroll
    for (int ch = 0; ch < NCH; ch++) inn += g_lossInn[(b * NCH + ch) * 256 + tid];
    if (m == n) {
        float td = 0.f;
        #pragma unroll
        for (int ch = 0; ch < NCH; ch++) td += g_lossTd[(b * NCH + ch) * 16 + m];
        s_sq[m] = inn; s_td[m] = td;
    }
    __syncthreads();
    float pd = 0.f;
    if (m != n) pd = sqrtf(fmaxf(s_sq[m] + s_sq[n] - 2.f * inn, 1e-6f));
    #pragma unroll
    for (int o = 16; o; o >>= 1) pd += __shfl_xor_sync(0xffffffffu, pd, o);
    if ((tid & 31) == 0) s_w[tid >> 5] = pd;
    __syncthreads();
    if (tid == 0) {
        float tot = 0.f;
        for (int w = 0; w < 8; w++) tot += s_w[w];
        float tc = 0.f;
        for (int mm = 0; mm < 16; mm++) tc += sqrtf(s_td[mm]);
        g_lossPart[b] = tc / 16.f - 0.5f * (tot / 240.f);   // LAM/2=0.5, M*(M-1)=240
    }
}

__global__ void k_loss_final(float* __restrict__ out, int off) {
    if (off >= 1 && threadIdx.x == 0 && blockIdx.x == 0) {
        float s = 0.f;
        for (int i = 0; i < NB; i++) s += g_lossPart[i];   // fixed order -> deterministic
        out[0] = s / (float)NB;
    }
}

// ---- multi-value butterfly: reduce 16 row sums across a warp in 16 shfls ----
__device__ __forceinline__ void warp_reduce16(float v[16], int lane,
                                              float& out, int& gheld) {
    const unsigned FULL = 0xffffffffu;
    #pragma unroll
    for (int i = 0; i < 8; i++) {
        float send = (lane & 16) ? v[i] : v[i + 8];
        float recv = __shfl_xor_sync(FULL, send, 16);
        v[i] = ((lane & 16) ? v[i + 8] : v[i]) + recv;
    }
    #pragma unroll
    for (int i = 0; i < 4; i++) {
        float send = (lane & 8) ? v[i] : v[i + 4];
        float recv = __shfl_xor_sync(FULL, send, 8);
        v[i] = ((lane & 8) ? v[i + 4] : v[i]) + recv;
    }
    #pragma unroll
    for (int i = 0; i < 2; i++) {
        float send = (lane & 4) ? v[i] : v[i + 2];
        float recv = __shfl_xor_sync(FULL, send, 4);
        v[i] = ((lane & 4) ? v[i + 2] : v[i]) + recv;
    }
    {
        float send = (lane & 2) ? v[0] : v[1];
        float recv = __shfl_xor_sync(FULL, send, 2);
        v[0] = ((lane & 2) ? v[1] : v[0]) + recv;
    }
    v[0] += __shfl_xor_sync(FULL, v[0], 1);
    gheld = ((lane >> 1) & 1) | (((lane >> 2) & 1) << 1)
          | (((lane >> 3) & 1) << 2) | (((lane >> 4) & 1) << 3);
    out = v[0];
}

// ---------------- stage 4: IPF, d-split cluster (local colsums, 32-float exchange) -------
// blockIdx.x = 2*b + rank; rank owns d in [rank*1000, rank*1000+1000) for ALL 32 g.
// Writes normalized y back to g_Y (coalesced); rounding stays in k_round.
__global__ void __cluster_dims__(2, 1, 1) __launch_bounds__(512, 1)
k_ipf(const int* __restrict__ ts) {
    const int tid = threadIdx.x, lane = tid & 31, warp = tid >> 5;
    uint32_t rank;
    asm("mov.u32 %0, %%cluster_ctarank;" : "=r"(rank));
    const int b = blockIdx.x >> 1;
    const int dBase = (int)rank * NDH;
    float* yg = g_Y + (size_t)b * NG * ND;
    const int* tsb = ts + (size_t)b * ND;

    __shared__ float s_red[16 * 32];    // [warp][g]
    __shared__ float s_x[2][32];        // row-partial exchange (double-buffered)
    __shared__ float s_R[32], s_rowfac[32];

    const uint32_t myX = smem_u32(&s_x[0][0]);
    const uint32_t peerX = mapa_u32(myX, rank ^ 1u);

    int dIdx[2]; bool val[2];
    float C0[2], colsum[2], yv[NG][2];
    #pragma unroll
    for (int c = 0; c < 2; c++) {
        int dl = c * 512 + tid;
        dIdx[c] = dBase + dl;
        val[c] = dl < NDH;
        C0[c] = val[c] ? fmaxf((float)__ldg(tsb + dIdx[c]), 0.f) : 0.f;
        colsum[c] = 0.f;
    }
    #pragma unroll
    for (int g = 0; g < NG; g++)
        #pragma unroll
        for (int c = 0; c < 2; c++) {
            yv[g][c] = val[c] ? fmaxf(yg[(size_t)g * ND + dIdx[c]], 0.f) : 0.f;
            colsum[c] += yv[g][c];
        }

    auto row_reduce_to_smem = [&]() {
        float v[16]; float o; int gh;
        #pragma unroll
        for (int i = 0; i < 16; i++) v[i] = yv[i][0] + yv[i][1];
        warp_reduce16(v, lane, o, gh);
        if (!(lane & 1)) s_red[warp * 32 + gh] = o;
        #pragma unroll
        for (int i = 0; i < 16; i++) v[i] = yv[16 + i][0] + yv[16 + i][1];
        warp_reduce16(v, lane, o, gh);
        if (!(lane & 1)) s_red[warp * 32 + 16 + gh] = o;
    };

    // initial row anchors R (global, pre-smoothing) — exchange buf 0
    row_reduce_to_smem();
    __syncthreads();
    if (tid < 32) {
        float s = 0.f;
        #pragma unroll
        for (int w = 0; w < 16; w++) s += s_red[w * 32 + tid];
        s_x[0][tid] = s;
    }
    asm volatile("barrier.cluster.arrive.aligned;" ::: "memory");
    asm volatile("barrier.cluster.wait.aligned;" ::: "memory");
    if (tid < 32) {
        float pv;
        asm volatile("ld.shared::cluster.f32 %0, [%1];"
                     : "=f"(pv) : "r"(peerX + (uint32_t)tid * 4u));
        s_R[tid] = s_x[0][tid] + pv;
    }
    __syncthreads();

    // col_zero smoothing (dead in practice — softplus > 0 — kept for exactness; local)
    #pragma unroll
    for (int c = 0; c < 2; c++) {
        if (val[c] && colsum[c] <= 0.f && C0[c] > 0.f) {
            #pragma unroll
            for (int g = 0; g < NG; g++) yv[g][c] += 1e-8f;
            colsum[c] += 32.f * 1e-8f;
        }
    }

    for (int it = 0; it < 60; it++) {
        float cf0 = fminf(fmaxf(C0[0] / fmaxf(colsum[0], EPSC), 0.75f), 1.25f);
        float cf1 = fminf(fmaxf(C0[1] / fmaxf(colsum[1], EPSC), 0.75f), 1.25f);
        #pragma unroll
        for (int g = 0; g < NG; g++) { yv[g][0] *= cf0; yv[g][1] *= cf1; }
        row_reduce_to_smem();
        __syncthreads();
        int buf = (it + 1) & 1;
        if (tid < 32) {
            float s = 0.f;
            #pragma unroll
            for (int w = 0; w < 16; w++) s += s_red[w * 32 + tid];
            s_x[buf][tid] = s;
        }
        asm volatile("barrier.cluster.arrive.aligned;" ::: "memory");
        asm volatile("barrier.cluster.wait.aligned;" ::: "memory");
        if (tid < 32) {
            float pv;
            asm volatile("ld.shared::cluster.f32 %0, [%1];"
                         : "=f"(pv) : "r"(peerX + (uint32_t)(buf * 32 + tid) * 4u));
            float rowsum = s_x[buf][tid] + pv;
            s_rowfac[tid] = fminf(fmaxf(s_R[tid] / fmaxf(rowsum, EPSC), 0.75f), 1.25f);
        }
        __syncthreads();
        colsum[0] = 0.f; colsum[1] = 0.f;
        #pragma unroll
        for (int g = 0; g < NG; g++) {
            float rf = s_rowfac[g];
            float v0 = yv[g][0] * rf, v1 = yv[g][1] * rf;
            yv[g][0] = v0; yv[g][1] = v1;
            colsum[0] += v0; colsum[1] += v1;
        }
    }

    // final column normalization (no clamp) + coalesced write-back
    {
        float f0 = C0[0] / fmaxf(colsum[0], EPSC);
        float f1 = C0[1] / fmaxf(colsum[1], EPSC);
        #pragma unroll
        for (int g = 0; g < NG; g++) {
            if (val[0]) yg[(size_t)g * ND + dIdx[0]] = yv[g][0] * f0;
            if (val[1]) yg[(size_t)g * ND + dIdx[1]] = yv[g][1] * f1;
        }
    }

    // peer must finish reading our smem before exit
    asm volatile("barrier.cluster.arrive.aligned;" ::: "memory");
    asm volatile("barrier.cluster.wait.aligned;" ::: "memory");
}

// ---------------- stage 5: exact integerization (smem-transposed tiles, 2048 CTAs) -------
__global__ void k_round(const int* __restrict__ ts, float* __restrict__ out, int off) {
    const unsigned FULL = 0xffffffffu;
    const int b = blockIdx.y;
    const int d0 = blockIdx.x * 64;
    const int tid = threadIdx.x, lane = tid & 31, warp = tid >> 5;
    __shared__ float sy[32 * 65];
    __shared__ int   so[32 * 65];

    #pragma unroll
    for (int i = 0; i < 8; i++) {       // coalesced load of 32g x 64d tile
        int idx = tid + i * 256;
        int row = idx >> 6, col = idx & 63;
        int d = d0 + col;
        sy[row * 65 + col] = (d < ND) ? g_Y[(size_t)(b * NG + row) * ND + d] : 0.f;
    }
    __syncthreads();

    #pragma unroll
    for (int rep = 0; rep < 8; rep++) {
        int dcol = warp * 8 + rep;      // warp-uniform column
        int d = d0 + dcol;
        if (d < ND) {
            float v = fmaxf(sy[lane * 65 + dcol], 0.f);   // lane = g
            float xf = floorf(v);
            int yi = (int)xf;
            float fr = v - xf;
            int t = ts[(size_t)b * ND + d];

            int s = __reduce_add_sync(FULL, yi);
            int need = t - s;
            int pos = need > 0 ? need : 0;
            int q = pos >> 5;
            yi += q;
            int r = pos - (q << 5);
            if (r > 0) {
                int cnt = 0;
                #pragma unroll
                for (int k = 1; k < 32; k++) {
                    int j = (lane + k) & 31;
                    float o = __shfl_sync(FULL, fr, j);
                    cnt += (o > fr) || (o == fr && j < lane);
                }
                if (cnt < r) yi += 1;
            }

            int s2 = __reduce_add_sync(FULL, yi);
            int need2 = t - s2;
            int neg = need2 < 0 ? -need2 : 0;
            neg = neg < s2 ? neg : s2;
            if (neg > 0) {
                int q2 = neg >> 5;
                int yb = yi;
                yi -= q2; if (yi < 0) yi = 0;
                int removed = __reduce_add_sync(FULL, yb - yi);
                int r2 = neg - removed;
                if (r2 > 0) {
                    float fm = (yi > 0) ? fr : __int_as_float(0x7f800000);  // +inf
                    int cnt2 = 0;
                    #pragma unroll
                    for (int k = 1; k < 32; k++) {
                        int j = (lane + k) & 31;
                        float o = __shfl_sync(FULL, fm, j);
                        cnt2 += (o < fm) || (o == fm && j < lane);
                    }
                    if (cnt2 < r2) yi -= 1;
                    if (yi < 0) yi = 0;
                }
            }
            so[lane * 65 + dcol] = yi;
        }
    }
    __syncthreads();

    #pragma unroll
    for (int i = 0; i < 8; i++) {       // coalesced store
        int idx = tid + i * 256;
        int row = idx >> 6, col = idx & 63;
        int d = d0 + col;
        if (d < ND)
            out[(size_t)off + (size_t)(b * NG + row) * ND + d] = (float)so[row * 65 + col];
    }
}

// ---------------- launch (pure kernel launches; no runtime API calls) ----------------
extern "C" void kernel_launch(void* const* d_in, const int* in_sizes, int n_in,
                              void* d_out, int out_size) {
    const float* x      = (const float*)d_in[0];   // [2048,256]
    const float* target = (const float*)d_in[1];   // [64,2000]
    const int*   tsum   = (const int*)  d_in[2];   // [64,2000]
    const float* W      = (const float*)d_in[3];   // [272,2000]
    const float* bias   = (const float*)d_in[4];   // [2000]
    const float* nl     = (const float*)d_in[5];   // [32768,16]
    const float* ns     = (const float*)d_in[6];   // [2048,16]
    float* out = (float*)d_out;

    int off = out_size - NB * NG * ND;             // expected 1 (loss scalar first)
    if (off < 0) off = 0;

    // 1) sample GEMM with softplus (f32x2 packed math): g_Y[2048,2000]
    k_gemm1<<<dim3(16, 16), 256>>>(x, ns, W, bias);
    // 2) tiny loss-path GEMM (group-reduce folded): g_Tp
    k_gemmT<<<dim3(8, 8, 4), 256>>>(x, W, bias);
    // 3) loss: partials (Ns folded, P rebuilt on the fly) -> combine -> final sum
    k_loss_part<<<dim3(NCH, NB), 256>>>(target, W, nl);
    k_loss_comb<<<NB, 256>>>();
    k_loss_final<<<1, 32>>>(out, off);
    // 4) IPF: d-split 2-CTA cluster, local colsums, 32-float exchange
    k_ipf<<<2 * NB, 512>>>(tsum);
    // 5) exact integer rounding (tiled, coalesced, 2048 CTAs)
    k_round<<<dim3(32, NB), 256>>>(tsum, out, off);
}